// round 14
// baseline (speedup 1.0000x reference)
#include <cuda_runtime.h>
#include <cuda_fp16.h>

// ---------------- constants (match problem shape) ----------------
#define NMAX      100000
#define NNZMAX    3200000
#define DIMC      256
#define NCH       4        // row chunks per hop for SpMM||GEMM overlap
#define HOPSMAX   3

// ---------------- device scratch (no allocations allowed) ----------------
__device__ static __half g_Hn16[NMAX * DIMC];  // SpMM result per hop (fp16)
__device__ static __half g_H16a[NMAX * DIMC];  // H ping (fp16)
__device__ static __half g_H16b[NMAX * DIMC];  // H pong (fp16)
__device__ static int2   g_edges[NNZMAX];      // CSR: (col, val-as-bits) sorted by row
__device__ static int    g_cnt[NMAX];
__device__ static int    g_rowptr[NMAX + 1];
__device__ static int    g_woff[NMAX];

// ---------------- CSR build ----------------
__global__ void zero_cnt_kernel(int* cnt, int N) {
    int i = blockIdx.x * blockDim.x + threadIdx.x;
    if (i < N) cnt[i] = 0;
}

// 4 edges per thread: vector load + 4 independent atomics (MLP)
__global__ void hist_kernel(const int* __restrict__ rows, int* cnt, int nnz) {
    int e = (blockIdx.x * blockDim.x + threadIdx.x) * 4;
    if (e + 4 <= nnz) {
        int4 r = *(const int4*)(rows + e);
        atomicAdd(&cnt[r.x], 1);
        atomicAdd(&cnt[r.y], 1);
        atomicAdd(&cnt[r.z], 1);
        atomicAdd(&cnt[r.w], 1);
    } else {
        for (int k = e; k < nnz; k++) atomicAdd(&cnt[rows[k]], 1);
    }
}

// single-block exclusive scan over N counts (1024 threads, sequential chunks)
__global__ void scan_kernel(const int* __restrict__ cnt, int* row_ptr, int* woff,
                            int N, int nnz) {
    __shared__ int wsum[32];
    int tid = threadIdx.x;
    int CH = (N + 1023) / 1024;
    int base = tid * CH;
    int s = 0;
    for (int j = 0; j < CH; j++) {
        int i = base + j;
        if (i < N) s += cnt[i];
    }
    int v = s;
    #pragma unroll
    for (int d = 1; d < 32; d <<= 1) {
        int n = __shfl_up_sync(0xffffffffu, v, d);
        if ((tid & 31) >= d) v += n;
    }
    if ((tid & 31) == 31) wsum[tid >> 5] = v;
    __syncthreads();
    if (tid < 32) {
        int w = wsum[tid];
        #pragma unroll
        for (int d = 1; d < 32; d <<= 1) {
            int n = __shfl_up_sync(0xffffffffu, w, d);
            if (tid >= d) w += n;
        }
        wsum[tid] = w;
    }
    __syncthreads();
    int warp = tid >> 5;
    int excl = (v - s) + (warp > 0 ? wsum[warp - 1] : 0);
    int run = excl;
    for (int j = 0; j < CH; j++) {
        int i = base + j;
        if (i < N) {
            row_ptr[i] = run;
            woff[i]    = run;
            run += cnt[i];
        }
    }
    if (tid == 0) row_ptr[N] = nnz;
}

// 4 edges per thread: vector loads, 4 independent atomic+store pairs
__global__ void scatter_kernel(const int* __restrict__ rows,
                               const int* __restrict__ cols,
                               const float* __restrict__ vals,
                               int* woff, int2* edges, int nnz) {
    int e = (blockIdx.x * blockDim.x + threadIdx.x) * 4;
    if (e + 4 <= nnz) {
        int4   r = *(const int4*)(rows + e);
        int4   c = *(const int4*)(cols + e);
        float4 v = *(const float4*)(vals + e);
        int p0 = atomicAdd(&woff[r.x], 1);
        int p1 = atomicAdd(&woff[r.y], 1);
        int p2 = atomicAdd(&woff[r.z], 1);
        int p3 = atomicAdd(&woff[r.w], 1);
        edges[p0] = make_int2(c.x, __float_as_int(v.x));
        edges[p1] = make_int2(c.y, __float_as_int(v.y));
        edges[p2] = make_int2(c.z, __float_as_int(v.z));
        edges[p3] = make_int2(c.w, __float_as_int(v.w));
    } else {
        for (int k = e; k < nnz; k++) {
            int p = atomicAdd(&woff[rows[k]], 1);
            edges[p] = make_int2(cols[k], __float_as_int(vals[k]));
        }
    }
}

// ---------------- fp32 -> fp16 conversion (for the initial m) ----------------
__global__ void f2h_kernel(const float* __restrict__ src, __half* __restrict__ dst,
                           int n) {  // n = total elems / 2
    int i = blockIdx.x * blockDim.x + threadIdx.x;
    if (i < n) {
        float2 v = ((const float2*)src)[i];
        ((__half2*)dst)[i] = __floats2half2_rn(v.x, v.y);
    }
}

// ---------------- SpMM: warp per row, CSR, fp16 gather, fp16 out, 4-edge MLP
// Processes `rows` rows: row_ptr/Hn already offset by caller to the chunk base.
__global__ void spmm16_kernel(const __half* __restrict__ H,
                              const int* __restrict__ row_ptr,
                              const int2* __restrict__ edges,
                              __half* __restrict__ Hn, int rowsN) {
    int warp = (blockIdx.x * blockDim.x + threadIdx.x) >> 5;
    int lane = threadIdx.x & 31;
    if (warp >= rowsN) return;
    int start = row_ptr[warp];
    int end   = row_ptr[warp + 1];

    float acc[8];
    #pragma unroll
    for (int i = 0; i < 8; i++) acc[i] = 0.f;

    auto accum = [&](uint4 raw, float val) {
        const __half2* hh = (const __half2*)&raw;
        float2 f0 = __half22float2(hh[0]);
        float2 f1 = __half22float2(hh[1]);
        float2 f2 = __half22float2(hh[2]);
        float2 f3 = __half22float2(hh[3]);
        acc[0] += val * f0.x; acc[1] += val * f0.y;
        acc[2] += val * f1.x; acc[3] += val * f1.y;
        acc[4] += val * f2.x; acc[5] += val * f2.y;
        acc[6] += val * f3.x; acc[7] += val * f3.y;
    };

    for (int e0 = start; e0 < end; e0 += 32) {
        int idx = e0 + lane;
        int2 ed = make_int2(0, 0);
        if (idx < end) ed = edges[idx];
        int cnt = min(32, end - e0);
        int j = 0;
        for (; j + 4 <= cnt; j += 4) {
            int   c0 = __shfl_sync(0xffffffffu, ed.x, j + 0);
            int   c1 = __shfl_sync(0xffffffffu, ed.x, j + 1);
            int   c2 = __shfl_sync(0xffffffffu, ed.x, j + 2);
            int   c3 = __shfl_sync(0xffffffffu, ed.x, j + 3);
            float v0 = __int_as_float(__shfl_sync(0xffffffffu, ed.y, j + 0));
            float v1 = __int_as_float(__shfl_sync(0xffffffffu, ed.y, j + 1));
            float v2 = __int_as_float(__shfl_sync(0xffffffffu, ed.y, j + 2));
            float v3 = __int_as_float(__shfl_sync(0xffffffffu, ed.y, j + 3));
            uint4 r0 = ((const uint4*)(H + (size_t)c0 * DIMC))[lane];
            uint4 r1 = ((const uint4*)(H + (size_t)c1 * DIMC))[lane];
            uint4 r2 = ((const uint4*)(H + (size_t)c2 * DIMC))[lane];
            uint4 r3 = ((const uint4*)(H + (size_t)c3 * DIMC))[lane];
            accum(r0, v0);
            accum(r1, v1);
            accum(r2, v2);
            accum(r3, v3);
        }
        for (; j < cnt; j++) {
            int   col = __shfl_sync(0xffffffffu, ed.x, j);
            float val = __int_as_float(__shfl_sync(0xffffffffu, ed.y, j));
            uint4 raw = ((const uint4*)(H + (size_t)col * DIMC))[lane];
            accum(raw, val);
        }
    }
    __half2 o[4];
    o[0] = __floats2half2_rn(acc[0], acc[1]);
    o[1] = __floats2half2_rn(acc[2], acc[3]);
    o[2] = __floats2half2_rn(acc[4], acc[5]);
    o[3] = __floats2half2_rn(acc[6], acc[7]);
    ((uint4*)(Hn + (size_t)warp * DIMC))[lane] = *(uint4*)o;
}

// ---------------- tf32 tensor-core GEMM, fp16 A, 3-stage pipeline ----------
// out[M,256] = Hn16@Wn^T + Hc16@Ws^T + (bn+bs), optional ELU.
// All row pointers (Hn, Hc, out/out16) pre-offset to the chunk base; M = rows.
#define GSTR 20   // B smem row stride (floats): 16 k + 4 pad
#define ASTR 24   // A smem row stride (halves): 16 k + 8 pad

__device__ __forceinline__ unsigned f2tf32(float x) {
    unsigned r;
    asm("cvt.rna.tf32.f32 %0, %1;" : "=r"(r) : "f"(x));
    return r;
}
__device__ __forceinline__ unsigned h2tf32(__half h) {
    return __float_as_uint(__half2float(h));   // exact: fp16 mantissa fits tf32
}

__global__ __launch_bounds__(128)
void gemm_tf32_kernel(const __half* __restrict__ Hn, const __half* __restrict__ Hc,
                      const float* __restrict__ Wn, const float* __restrict__ Ws,
                      const float* __restrict__ bn, const float* __restrict__ bs,
                      float* __restrict__ out, __half* __restrict__ out16,
                      int M, int doElu) {
    __shared__ __half As[3][128 * ASTR];
    __shared__ float  Bs[3][128 * GSTR];

    int tid  = threadIdx.x;
    int lane = tid & 31;
    int wid  = tid >> 5;
    int grp  = lane >> 2;
    int tig  = lane & 3;
    int warpM = wid >> 1;
    int warpN = wid & 1;
    int rowBase = blockIdx.x * 128;
    int colBase = blockIdx.y * 128;

    int lf = tid & 3;
    int lr = tid >> 2;

    float c[4][8][4];
    #pragma unroll
    for (int mi = 0; mi < 4; mi++)
        #pragma unroll
        for (int ni = 0; ni < 8; ni++)
            #pragma unroll
            for (int r = 0; r < 4; r++) c[mi][ni][r] = 0.f;

    auto issue = [&](int it) {
        int k0 = it * 16;
        const __half* Asrc = (k0 < 256) ? Hn : Hc;
        const float*  Wsrc = (k0 < 256) ? Wn : Ws;
        int kOff = k0 & 255;
        int st = it % 3;
        #pragma unroll
        for (int i = 0; i < 2; i++) {
            int idx = tid + i * 128;
            int row = idx >> 1;
            int c8  = (idx & 1) * 8;
            int grow = rowBase + row;
            int ok = (grow < M);
            const __half* asrc = Asrc + (size_t)(ok ? grow : 0) * DIMC + kOff + c8;
            unsigned adst = (unsigned)__cvta_generic_to_shared(&As[st][row * ASTR + c8]);
            int asz = ok ? 16 : 0;
            asm volatile("cp.async.cg.shared.global [%0], [%1], 16, %2;\n"
                         :: "r"(adst), "l"(asrc), "r"(asz));
        }
        #pragma unroll
        for (int i = 0; i < 4; i++) {
            int row = lr + 32 * i;
            const float* bsrc = Wsrc + (size_t)(colBase + row) * DIMC + kOff + lf * 4;
            unsigned bdst = (unsigned)__cvta_generic_to_shared(&Bs[st][row * GSTR + lf * 4]);
            asm volatile("cp.async.cg.shared.global [%0], [%1], 16, %2;\n"
                         :: "r"(bdst), "l"(bsrc), "r"(16));
        }
        asm volatile("cp.async.commit_group;\n");
    };

    issue(0);
    issue(1);

    int st = 0;
    for (int it = 0; it < 32; it++) {
        if (it < 31) asm volatile("cp.async.wait_group 1;\n" ::: "memory");
        else         asm volatile("cp.async.wait_group 0;\n" ::: "memory");
        __syncthreads();
        if (it + 2 < 32) issue(it + 2);

        #pragma unroll
        for (int kk = 0; kk < 2; kk++) {
            unsigned a[4][4], b[8][2];
            int k = kk * 8 + tig;
            #pragma unroll
            for (int mi = 0; mi < 4; mi++) {
                int m0 = warpM * 64 + mi * 16 + grp;
                a[mi][0] = h2tf32(As[st][m0 * ASTR + k]);
                a[mi][1] = h2tf32(As[st][(m0 + 8) * ASTR + k]);
                a[mi][2] = h2tf32(As[st][m0 * ASTR + k + 4]);
                a[mi][3] = h2tf32(As[st][(m0 + 8) * ASTR + k + 4]);
            }
            #pragma unroll
            for (int ni = 0; ni < 8; ni++) {
                int n0 = warpN * 64 + ni * 8 + grp;
                b[ni][0] = f2tf32(Bs[st][n0 * GSTR + k]);
                b[ni][1] = f2tf32(Bs[st][n0 * GSTR + k + 4]);
            }
            #pragma unroll
            for (int mi = 0; mi < 4; mi++)
                #pragma unroll
                for (int ni = 0; ni < 8; ni++) {
                    asm volatile(
                        "mma.sync.aligned.m16n8k8.row.col.f32.tf32.tf32.f32 "
                        "{%0,%1,%2,%3}, {%4,%5,%6,%7}, {%8,%9}, {%0,%1,%2,%3};\n"
                        : "+f"(c[mi][ni][0]), "+f"(c[mi][ni][1]),
                          "+f"(c[mi][ni][2]), "+f"(c[mi][ni][3])
                        : "r"(a[mi][0]), "r"(a[mi][1]), "r"(a[mi][2]), "r"(a[mi][3]),
                          "r"(b[ni][0]), "r"(b[ni][1]));
                }
        }
        st = (st == 2) ? 0 : st + 1;
    }

    #pragma unroll
    for (int mi = 0; mi < 4; mi++) {
        #pragma unroll
        for (int r = 0; r < 2; r++) {
            int grow = rowBase + warpM * 64 + mi * 16 + grp + r * 8;
            if (grow >= M) continue;
            #pragma unroll
            for (int ni = 0; ni < 8; ni++) {
                int gcol = colBase + warpN * 64 + ni * 8 + tig * 2;
                float v0 = c[mi][ni][r * 2 + 0] + bn[gcol]     + bs[gcol];
                float v1 = c[mi][ni][r * 2 + 1] + bn[gcol + 1] + bs[gcol + 1];
                if (doElu) {
                    if (v0 < 0.f) v0 = expm1f(v0);
                    if (v1 < 0.f) v1 = expm1f(v1);
                }
                if (out)
                    *(float2*)(out + (size_t)grow * DIMC + gcol) = make_float2(v0, v1);
                else
                    *(__half2*)(out16 + (size_t)grow * DIMC + gcol) =
                        __floats2half2_rn(v0, v1);
            }
        }
    }
}

// ---------------- launch: chunked SpMM || GEMM software pipeline ------------
extern "C" void kernel_launch(void* const* d_in, const int* in_sizes, int n_in,
                              void* d_out, int out_size) {
    const float* m    = (const float*)d_in[0];
    const float* vals = (const float*)d_in[1];
    const float* Wn   = (const float*)d_in[2];
    const float* bn   = (const float*)d_in[3];
    const float* Ws   = (const float*)d_in[4];
    const float* bs   = (const float*)d_in[5];
    const int*   rows = (const int*)d_in[6];   // int32: JAX default x64-disabled
    const int*   cols = (const int*)d_in[7];

    int N    = in_sizes[0] / DIMC;
    int nnz  = in_sizes[1];
    int hops = in_sizes[2] / (DIMC * DIMC);
    if (hops > HOPSMAX) hops = HOPSMAX;

    __half *Hn16, *H16a, *H16b;
    int *cnt, *rowptr, *woff;
    int2* edges;
    cudaGetSymbolAddress((void**)&Hn16,   g_Hn16);
    cudaGetSymbolAddress((void**)&H16a,   g_H16a);
    cudaGetSymbolAddress((void**)&H16b,   g_H16b);
    cudaGetSymbolAddress((void**)&edges,  g_edges);
    cudaGetSymbolAddress((void**)&cnt,    g_cnt);
    cudaGetSymbolAddress((void**)&rowptr, g_rowptr);
    cudaGetSymbolAddress((void**)&woff,   g_woff);

    // fork stream for SpMM chunks; events for cross-stream deps
    cudaStream_t sS = 0;
    if (cudaStreamCreateWithFlags(&sS, cudaStreamNonBlocking) != cudaSuccess)
        sS = 0;   // fallback: single-stream, issue order respects all deps
    cudaEvent_t evInit;
    cudaEvent_t evS[HOPSMAX][NCH];
    cudaEvent_t evG[HOPSMAX];
    cudaEventCreateWithFlags(&evInit, cudaEventDisableTiming);
    for (int h = 0; h < HOPSMAX; h++) {
        cudaEventCreateWithFlags(&evG[h], cudaEventDisableTiming);
        for (int k = 0; k < NCH; k++)
            cudaEventCreateWithFlags(&evS[h][k], cudaEventDisableTiming);
    }

    // --- CSR build + f2h on origin stream ---
    zero_cnt_kernel<<<(N + 255) / 256, 256>>>(cnt, N);
    int e4 = (nnz + 3) / 4;
    hist_kernel<<<(e4 + 255) / 256, 256>>>(rows, cnt, nnz);
    scan_kernel<<<1, 1024>>>(cnt, rowptr, woff, N, nnz);
    scatter_kernel<<<(e4 + 255) / 256, 256>>>(rows, cols, vals, woff, edges, nnz);
    int nh2 = N * DIMC / 2;
    f2h_kernel<<<(nh2 + 255) / 256, 256>>>(m, H16a, nh2);
    cudaEventRecord(evInit, 0);
    cudaStreamWaitEvent(sS, evInit, 0);

    // --- hop loop, NCH row-chunks: S_k on sS, G_k on origin, events between ---
    float* out0 = (float*)d_out;
    int csz = ((N + NCH - 1) / NCH + 127) & ~127;   // 128-aligned chunk size

    __half* Hcur  = H16a;
    __half* Hnext = H16b;
    for (int h = 0; h < hops; h++) {
        int last = (h == hops - 1);
        // SpMM chunks on sS (hop h>0: first chunk waits for all hop h-1 GEMMs)
        if (h > 0) cudaStreamWaitEvent(sS, evG[h - 1], 0);
        for (int k = 0; k < NCH; k++) {
            int r0 = k * csz;
            int rcnt = N - r0; if (rcnt > csz) rcnt = csz;
            if (rcnt <= 0) { cudaEventRecord(evS[h][k], sS); continue; }
            int blocks = (rcnt * 32 + 255) / 256;
            spmm16_kernel<<<blocks, 256, 0, sS>>>(Hcur, rowptr + r0, edges,
                                                  Hn16 + (size_t)r0 * DIMC, rcnt);
            cudaEventRecord(evS[h][k], sS);
        }
        // GEMM chunks on origin stream
        for (int k = 0; k < NCH; k++) {
            int r0 = k * csz;
            int rcnt = N - r0; if (rcnt > csz) rcnt = csz;
            if (rcnt <= 0) continue;
            cudaStreamWaitEvent(0, evS[h][k], 0);
            dim3 gg((rcnt + 127) / 128, DIMC / 128);
            gemm_tf32_kernel<<<gg, 128>>>(Hn16 + (size_t)r0 * DIMC,
                                          Hcur + (size_t)r0 * DIMC,
                                          Wn + (size_t)h * DIMC * DIMC,
                                          Ws + (size_t)h * DIMC * DIMC,
                                          bn + (size_t)h * DIMC,
                                          bs + (size_t)h * DIMC,
                                          last ? out0 + (size_t)r0 * DIMC : nullptr,
                                          last ? nullptr : Hnext + (size_t)r0 * DIMC,
                                          rcnt, !last);
        }
        cudaEventRecord(evG[h], 0);
        __half* t = Hcur; Hcur = Hnext; Hnext = t;
    }
}

// round 15
// speedup vs baseline: 1.0594x; 1.0594x over previous
#include <cuda_runtime.h>
#include <cuda_fp16.h>

// ---------------- constants (match problem shape) ----------------
#define NMAX      100000
#define NNZMAX    3200000
#define DIMC      256

// ---------------- device scratch (no allocations allowed) ----------------
__device__ static __half g_Hn16[NMAX * DIMC];  // SpMM result per hop (fp16)
__device__ static __half g_H16a[NMAX * DIMC];  // H ping (fp16)
__device__ static __half g_H16b[NMAX * DIMC];  // H pong (fp16)
__device__ static int2   g_edges[NNZMAX];      // CSR: (col, val-as-bits) sorted by row
__device__ static int    g_cnt[NMAX];
__device__ static int    g_rowptr[NMAX + 1];
__device__ static int    g_woff[NMAX];

// ---------------- CSR build ----------------
// 4 edges per thread: vector load + 4 independent atomics (MLP)
__global__ void hist_kernel(const int* __restrict__ rows, int* cnt, int nnz) {
    int e = (blockIdx.x * blockDim.x + threadIdx.x) * 4;
    if (e + 4 <= nnz) {
        int4 r = *(const int4*)(rows + e);
        atomicAdd(&cnt[r.x], 1);
        atomicAdd(&cnt[r.y], 1);
        atomicAdd(&cnt[r.z], 1);
        atomicAdd(&cnt[r.w], 1);
    } else {
        for (int k = e; k < nnz; k++) atomicAdd(&cnt[rows[k]], 1);
    }
}

// single-block exclusive scan over N counts (1024 threads, sequential chunks)
__global__ void scan_kernel(const int* __restrict__ cnt, int* row_ptr, int* woff,
                            int N, int nnz) {
    __shared__ int wsum[32];
    int tid = threadIdx.x;
    int CH = (N + 1023) / 1024;
    int base = tid * CH;
    int s = 0;
    for (int j = 0; j < CH; j++) {
        int i = base + j;
        if (i < N) s += cnt[i];
    }
    int v = s;
    #pragma unroll
    for (int d = 1; d < 32; d <<= 1) {
        int n = __shfl_up_sync(0xffffffffu, v, d);
        if ((tid & 31) >= d) v += n;
    }
    if ((tid & 31) == 31) wsum[tid >> 5] = v;
    __syncthreads();
    if (tid < 32) {
        int w = wsum[tid];
        #pragma unroll
        for (int d = 1; d < 32; d <<= 1) {
            int n = __shfl_up_sync(0xffffffffu, w, d);
            if (tid >= d) w += n;
        }
        wsum[tid] = w;
    }
    __syncthreads();
    int warp = tid >> 5;
    int excl = (v - s) + (warp > 0 ? wsum[warp - 1] : 0);
    int run = excl;
    for (int j = 0; j < CH; j++) {
        int i = base + j;
        if (i < N) {
            row_ptr[i] = run;
            woff[i]    = run;
            run += cnt[i];
        }
    }
    if (tid == 0) row_ptr[N] = nnz;
}

// 4 edges per thread: vector loads, 4 independent atomic+store pairs
__global__ void scatter_kernel(const int* __restrict__ rows,
                               const int* __restrict__ cols,
                               const float* __restrict__ vals,
                               int* woff, int2* edges, int nnz) {
    int e = (blockIdx.x * blockDim.x + threadIdx.x) * 4;
    if (e + 4 <= nnz) {
        int4   r = *(const int4*)(rows + e);
        int4   c = *(const int4*)(cols + e);
        float4 v = *(const float4*)(vals + e);
        int p0 = atomicAdd(&woff[r.x], 1);
        int p1 = atomicAdd(&woff[r.y], 1);
        int p2 = atomicAdd(&woff[r.z], 1);
        int p3 = atomicAdd(&woff[r.w], 1);
        edges[p0] = make_int2(c.x, __float_as_int(v.x));
        edges[p1] = make_int2(c.y, __float_as_int(v.y));
        edges[p2] = make_int2(c.z, __float_as_int(v.z));
        edges[p3] = make_int2(c.w, __float_as_int(v.w));
    } else {
        for (int k = e; k < nnz; k++) {
            int p = atomicAdd(&woff[rows[k]], 1);
            edges[p] = make_int2(cols[k], __float_as_int(vals[k]));
        }
    }
}

// ---------------- fp32 -> fp16 conversion (for the initial m) ----------------
__global__ void f2h_kernel(const float* __restrict__ src, __half* __restrict__ dst,
                           int n) {  // n = total elems / 2
    int i = blockIdx.x * blockDim.x + threadIdx.x;
    if (i < n) {
        float2 v = ((const float2*)src)[i];
        ((__half2*)dst)[i] = __floats2half2_rn(v.x, v.y);
    }
}

// ---------------- SpMM: warp per row, CSR, fp16 gather, fp16 out, 4-edge MLP
__global__ void spmm16_kernel(const __half* __restrict__ H,
                              const int* __restrict__ row_ptr,
                              const int2* __restrict__ edges,
                              __half* __restrict__ Hn, int N) {
    int warp = (blockIdx.x * blockDim.x + threadIdx.x) >> 5;
    int lane = threadIdx.x & 31;
    if (warp >= N) return;
    int start = row_ptr[warp];
    int end   = row_ptr[warp + 1];

    float acc[8];
    #pragma unroll
    for (int i = 0; i < 8; i++) acc[i] = 0.f;

    auto accum = [&](uint4 raw, float val) {
        const __half2* hh = (const __half2*)&raw;
        float2 f0 = __half22float2(hh[0]);
        float2 f1 = __half22float2(hh[1]);
        float2 f2 = __half22float2(hh[2]);
        float2 f3 = __half22float2(hh[3]);
        acc[0] += val * f0.x; acc[1] += val * f0.y;
        acc[2] += val * f1.x; acc[3] += val * f1.y;
        acc[4] += val * f2.x; acc[5] += val * f2.y;
        acc[6] += val * f3.x; acc[7] += val * f3.y;
    };

    for (int e0 = start; e0 < end; e0 += 32) {
        int idx = e0 + lane;
        int2 ed = make_int2(0, 0);
        if (idx < end) ed = edges[idx];
        int cnt = min(32, end - e0);
        int j = 0;
        for (; j + 4 <= cnt; j += 4) {
            int   c0 = __shfl_sync(0xffffffffu, ed.x, j + 0);
            int   c1 = __shfl_sync(0xffffffffu, ed.x, j + 1);
            int   c2 = __shfl_sync(0xffffffffu, ed.x, j + 2);
            int   c3 = __shfl_sync(0xffffffffu, ed.x, j + 3);
            float v0 = __int_as_float(__shfl_sync(0xffffffffu, ed.y, j + 0));
            float v1 = __int_as_float(__shfl_sync(0xffffffffu, ed.y, j + 1));
            float v2 = __int_as_float(__shfl_sync(0xffffffffu, ed.y, j + 2));
            float v3 = __int_as_float(__shfl_sync(0xffffffffu, ed.y, j + 3));
            uint4 r0 = ((const uint4*)(H + (size_t)c0 * DIMC))[lane];
            uint4 r1 = ((const uint4*)(H + (size_t)c1 * DIMC))[lane];
            uint4 r2 = ((const uint4*)(H + (size_t)c2 * DIMC))[lane];
            uint4 r3 = ((const uint4*)(H + (size_t)c3 * DIMC))[lane];
            accum(r0, v0);
            accum(r1, v1);
            accum(r2, v2);
            accum(r3, v3);
        }
        for (; j < cnt; j++) {
            int   col = __shfl_sync(0xffffffffu, ed.x, j);
            float val = __int_as_float(__shfl_sync(0xffffffffu, ed.y, j));
            uint4 raw = ((const uint4*)(H + (size_t)col * DIMC))[lane];
            accum(raw, val);
        }
    }
    __half2 o[4];
    o[0] = __floats2half2_rn(acc[0], acc[1]);
    o[1] = __floats2half2_rn(acc[2], acc[3]);
    o[2] = __floats2half2_rn(acc[4], acc[5]);
    o[3] = __floats2half2_rn(acc[6], acc[7]);
    ((uint4*)(Hn + (size_t)warp * DIMC))[lane] = *(uint4*)o;
}

// ---------------- tf32 tensor-core GEMM, fp16 A, 3-stage pipeline ----------
// out[M,256] = Hn16@Wn^T + Hc16@Ws^T + (bn+bs), optional ELU.
// K=512 logical (k<256 -> Hn16/Wn, else Hc16/Ws). Block 128x128, 4 warps
// (2x2), warp 64x64, BK=16. 3-stage cp.async ring, ONE __syncthreads/iter.
#define GSTR 20   // B smem row stride (floats): 16 k + 4 pad
#define ASTR 24   // A smem row stride (halves): 16 k + 8 pad

__device__ __forceinline__ unsigned f2tf32(float x) {
    unsigned r;
    asm("cvt.rna.tf32.f32 %0, %1;" : "=r"(r) : "f"(x));
    return r;
}
__device__ __forceinline__ unsigned h2tf32(__half h) {
    return __float_as_uint(__half2float(h));   // exact: fp16 mantissa fits tf32
}

__global__ __launch_bounds__(128)
void gemm_tf32_kernel(const __half* __restrict__ Hn, const __half* __restrict__ Hc,
                      const float* __restrict__ Wn, const float* __restrict__ Ws,
                      const float* __restrict__ bn, const float* __restrict__ bs,
                      float* __restrict__ out, __half* __restrict__ out16,
                      int M, int doElu) {
    __shared__ __half As[3][128 * ASTR];
    __shared__ float  Bs[3][128 * GSTR];

    int tid  = threadIdx.x;
    int lane = tid & 31;
    int wid  = tid >> 5;
    int grp  = lane >> 2;
    int tig  = lane & 3;
    int warpM = wid >> 1;
    int warpN = wid & 1;
    int rowBase = blockIdx.x * 128;
    int colBase = blockIdx.y * 128;

    int lf = tid & 3;
    int lr = tid >> 2;

    float c[4][8][4];
    #pragma unroll
    for (int mi = 0; mi < 4; mi++)
        #pragma unroll
        for (int ni = 0; ni < 8; ni++)
            #pragma unroll
            for (int r = 0; r < 4; r++) c[mi][ni][r] = 0.f;

    auto issue = [&](int it) {
        int k0 = it * 16;
        const __half* Asrc = (k0 < 256) ? Hn : Hc;
        const float*  Wsrc = (k0 < 256) ? Wn : Ws;
        int kOff = k0 & 255;
        int st = it % 3;
        #pragma unroll
        for (int i = 0; i < 2; i++) {
            int idx = tid + i * 128;
            int row = idx >> 1;
            int c8  = (idx & 1) * 8;
            int grow = rowBase + row;
            int ok = (grow < M);
            const __half* asrc = Asrc + (size_t)(ok ? grow : 0) * DIMC + kOff + c8;
            unsigned adst = (unsigned)__cvta_generic_to_shared(&As[st][row * ASTR + c8]);
            int asz = ok ? 16 : 0;
            asm volatile("cp.async.cg.shared.global [%0], [%1], 16, %2;\n"
                         :: "r"(adst), "l"(asrc), "r"(asz));
        }
        #pragma unroll
        for (int i = 0; i < 4; i++) {
            int row = lr + 32 * i;
            const float* bsrc = Wsrc + (size_t)(colBase + row) * DIMC + kOff + lf * 4;
            unsigned bdst = (unsigned)__cvta_generic_to_shared(&Bs[st][row * GSTR + lf * 4]);
            asm volatile("cp.async.cg.shared.global [%0], [%1], 16, %2;\n"
                         :: "r"(bdst), "l"(bsrc), "r"(16));
        }
        asm volatile("cp.async.commit_group;\n");
    };

    issue(0);
    issue(1);

    int st = 0;
    for (int it = 0; it < 32; it++) {
        if (it < 31) asm volatile("cp.async.wait_group 1;\n" ::: "memory");
        else         asm volatile("cp.async.wait_group 0;\n" ::: "memory");
        __syncthreads();
        if (it + 2 < 32) issue(it + 2);

        #pragma unroll
        for (int kk = 0; kk < 2; kk++) {
            unsigned a[4][4], b[8][2];
            int k = kk * 8 + tig;
            #pragma unroll
            for (int mi = 0; mi < 4; mi++) {
                int m0 = warpM * 64 + mi * 16 + grp;
                a[mi][0] = h2tf32(As[st][m0 * ASTR + k]);
                a[mi][1] = h2tf32(As[st][(m0 + 8) * ASTR + k]);
                a[mi][2] = h2tf32(As[st][m0 * ASTR + k + 4]);
                a[mi][3] = h2tf32(As[st][(m0 + 8) * ASTR + k + 4]);
            }
            #pragma unroll
            for (int ni = 0; ni < 8; ni++) {
                int n0 = warpN * 64 + ni * 8 + grp;
                b[ni][0] = f2tf32(Bs[st][n0 * GSTR + k]);
                b[ni][1] = f2tf32(Bs[st][n0 * GSTR + k + 4]);
            }
            #pragma unroll
            for (int mi = 0; mi < 4; mi++)
                #pragma unroll
                for (int ni = 0; ni < 8; ni++) {
                    asm volatile(
                        "mma.sync.aligned.m16n8k8.row.col.f32.tf32.tf32.f32 "
                        "{%0,%1,%2,%3}, {%4,%5,%6,%7}, {%8,%9}, {%0,%1,%2,%3};\n"
                        : "+f"(c[mi][ni][0]), "+f"(c[mi][ni][1]),
                          "+f"(c[mi][ni][2]), "+f"(c[mi][ni][3])
                        : "r"(a[mi][0]), "r"(a[mi][1]), "r"(a[mi][2]), "r"(a[mi][3]),
                          "r"(b[ni][0]), "r"(b[ni][1]));
                }
        }
        st = (st == 2) ? 0 : st + 1;
    }

    #pragma unroll
    for (int mi = 0; mi < 4; mi++) {
        #pragma unroll
        for (int r = 0; r < 2; r++) {
            int grow = rowBase + warpM * 64 + mi * 16 + grp + r * 8;
            if (grow >= M) continue;
            #pragma unroll
            for (int ni = 0; ni < 8; ni++) {
                int gcol = colBase + warpN * 64 + ni * 8 + tig * 2;
                float v0 = c[mi][ni][r * 2 + 0] + bn[gcol]     + bs[gcol];
                float v1 = c[mi][ni][r * 2 + 1] + bn[gcol + 1] + bs[gcol + 1];
                if (doElu) {
                    if (v0 < 0.f) v0 = expm1f(v0);
                    if (v1 < 0.f) v1 = expm1f(v1);
                }
                if (out)
                    *(float2*)(out + (size_t)grow * DIMC + gcol) = make_float2(v0, v1);
                else
                    *(__half2*)(out16 + (size_t)grow * DIMC + gcol) =
                        __floats2half2_rn(v0, v1);
            }
        }
    }
}

// ---------------- launch ----------------
extern "C" void kernel_launch(void* const* d_in, const int* in_sizes, int n_in,
                              void* d_out, int out_size) {
    const float* m    = (const float*)d_in[0];
    const float* vals = (const float*)d_in[1];
    const float* Wn   = (const float*)d_in[2];
    const float* bn   = (const float*)d_in[3];
    const float* Ws   = (const float*)d_in[4];
    const float* bs   = (const float*)d_in[5];
    const int*   rows = (const int*)d_in[6];   // int32: JAX default x64-disabled
    const int*   cols = (const int*)d_in[7];

    int N    = in_sizes[0] / DIMC;
    int nnz  = in_sizes[1];
    int hops = in_sizes[2] / (DIMC * DIMC);

    __half *Hn16, *H16a, *H16b;
    int *cnt, *rowptr, *woff;
    int2* edges;
    cudaGetSymbolAddress((void**)&Hn16,   g_Hn16);
    cudaGetSymbolAddress((void**)&H16a,   g_H16a);
    cudaGetSymbolAddress((void**)&H16b,   g_H16b);
    cudaGetSymbolAddress((void**)&edges,  g_edges);
    cudaGetSymbolAddress((void**)&cnt,    g_cnt);
    cudaGetSymbolAddress((void**)&rowptr, g_rowptr);
    cudaGetSymbolAddress((void**)&woff,   g_woff);

    // fork stream: f2h runs concurrently with the CSR build (single fork-join)
    cudaStream_t sB = 0;
    if (cudaStreamCreateWithFlags(&sB, cudaStreamNonBlocking) != cudaSuccess)
        sB = 0;   // fallback: same stream, order still valid
    cudaEvent_t evFork, evF2H;
    cudaEventCreateWithFlags(&evFork, cudaEventDisableTiming);
    cudaEventCreateWithFlags(&evF2H,  cudaEventDisableTiming);

    cudaEventRecord(evFork, 0);
    cudaStreamWaitEvent(sB, evFork, 0);

    // stream B: fp16 shadow of initial H
    int nh2 = N * DIMC / 2;
    f2h_kernel<<<(nh2 + 255) / 256, 256, 0, sB>>>(m, H16a, nh2);
    cudaEventRecord(evF2H, sB);

    // origin stream: CSR build (memset instead of zero kernel)
    cudaMemsetAsync(cnt, 0, (size_t)N * sizeof(int), 0);
    int e4 = (nnz + 3) / 4;
    hist_kernel<<<(e4 + 255) / 256, 256>>>(rows, cnt, nnz);
    scan_kernel<<<1, 1024>>>(cnt, rowptr, woff, N, nnz);
    scatter_kernel<<<(e4 + 255) / 256, 256>>>(rows, cols, vals, woff, edges, nnz);

    // join: SpMM needs both CSR (origin) and H16a (sB)
    cudaStreamWaitEvent(0, evF2H, 0);

    // --- hop loop (single stream, proven fastest structure) ---
    float* out0 = (float*)d_out;
    int spmm_blocks = (N * 32 + 255) / 256;     // warp per row
    dim3 ggrid((N + 127) / 128, DIMC / 128);

    __half* Hcur  = H16a;
    __half* Hnext = H16b;
    for (int i = 0; i < hops; i++) {
        spmm16_kernel<<<spmm_blocks, 256>>>(Hcur, rowptr, edges, Hn16, N);
        int last = (i == hops - 1);
        gemm_tf32_kernel<<<ggrid, 128>>>(Hn16, Hcur,
                                         Wn + (size_t)i * DIMC * DIMC,
                                         Ws + (size_t)i * DIMC * DIMC,
                                         bn + (size_t)i * DIMC,
                                         bs + (size_t)i * DIMC,
                                         last ? out0 : nullptr,
                                         last ? nullptr : Hnext,
                                         N, !last);
        __half* t = Hcur; Hcur = Hnext; Hnext = t;
    }
}

// round 16
// speedup vs baseline: 1.0800x; 1.0195x over previous
#include <cuda_runtime.h>
#include <cuda_fp16.h>

// ---------------- constants (match problem shape) ----------------
#define NMAX      100000
#define NNZMAX    3200000
#define DIMC      256

// ---------------- device scratch (no allocations allowed) ----------------
__device__ static __half g_Hn16[NMAX * DIMC];  // SpMM result per hop (fp16)
__device__ static __half g_H16a[NMAX * DIMC];  // H ping (fp16)
__device__ static __half g_H16b[NMAX * DIMC];  // H pong (fp16)
__device__ static int2   g_edges[NNZMAX];      // CSR: (col, val-as-bits) sorted by row
__device__ static int    g_cnt[NMAX];
__device__ static int    g_rowptr[NMAX + 1];
__device__ static int    g_woff[NMAX];

// ---------------- CSR build ----------------
// 4 edges per thread (vector load + 4 independent atomics) FUSED with the
// fp32->fp16 conversion of m (streaming work hides under atomic latency).
__global__ void hist_f2h_kernel(const int* __restrict__ rows, int* cnt, int nnz,
                                const float* __restrict__ msrc,
                                __half* __restrict__ mdst, int nh2) {
    int t = blockIdx.x * blockDim.x + threadIdx.x;
    int e = t * 4;
    if (e + 4 <= nnz) {
        int4 r = *(const int4*)(rows + e);
        atomicAdd(&cnt[r.x], 1);
        atomicAdd(&cnt[r.y], 1);
        atomicAdd(&cnt[r.z], 1);
        atomicAdd(&cnt[r.w], 1);
    } else {
        for (int k = e; k < nnz; k++) atomicAdd(&cnt[rows[k]], 1);
    }
    // strided fp32->fp16 conversion (nh2 = elems/2), grid-stride over all threads
    int nth = gridDim.x * blockDim.x;
    for (int i = t; i < nh2; i += nth) {
        float2 v = ((const float2*)msrc)[i];
        ((__half2*)mdst)[i] = __floats2half2_rn(v.x, v.y);
    }
}

// single-block exclusive scan over N counts (1024 threads, sequential chunks)
__global__ void scan_kernel(const int* __restrict__ cnt, int* row_ptr, int* woff,
                            int N, int nnz) {
    __shared__ int wsum[32];
    int tid = threadIdx.x;
    int CH = (N + 1023) / 1024;
    int base = tid * CH;
    int s = 0;
    for (int j = 0; j < CH; j++) {
        int i = base + j;
        if (i < N) s += cnt[i];
    }
    int v = s;
    #pragma unroll
    for (int d = 1; d < 32; d <<= 1) {
        int n = __shfl_up_sync(0xffffffffu, v, d);
        if ((tid & 31) >= d) v += n;
    }
    if ((tid & 31) == 31) wsum[tid >> 5] = v;
    __syncthreads();
    if (tid < 32) {
        int w = wsum[tid];
        #pragma unroll
        for (int d = 1; d < 32; d <<= 1) {
            int n = __shfl_up_sync(0xffffffffu, w, d);
            if (tid >= d) w += n;
        }
        wsum[tid] = w;
    }
    __syncthreads();
    int warp = tid >> 5;
    int excl = (v - s) + (warp > 0 ? wsum[warp - 1] : 0);
    int run = excl;
    for (int j = 0; j < CH; j++) {
        int i = base + j;
        if (i < N) {
            row_ptr[i] = run;
            woff[i]    = run;
            run += cnt[i];
        }
    }
    if (tid == 0) row_ptr[N] = nnz;
}

// 4 edges per thread: vector loads, 4 independent atomic+store pairs
__global__ void scatter_kernel(const int* __restrict__ rows,
                               const int* __restrict__ cols,
                               const float* __restrict__ vals,
                               int* woff, int2* edges, int nnz) {
    int e = (blockIdx.x * blockDim.x + threadIdx.x) * 4;
    if (e + 4 <= nnz) {
        int4   r = *(const int4*)(rows + e);
        int4   c = *(const int4*)(cols + e);
        float4 v = *(const float4*)(vals + e);
        int p0 = atomicAdd(&woff[r.x], 1);
        int p1 = atomicAdd(&woff[r.y], 1);
        int p2 = atomicAdd(&woff[r.z], 1);
        int p3 = atomicAdd(&woff[r.w], 1);
        edges[p0] = make_int2(c.x, __float_as_int(v.x));
        edges[p1] = make_int2(c.y, __float_as_int(v.y));
        edges[p2] = make_int2(c.z, __float_as_int(v.z));
        edges[p3] = make_int2(c.w, __float_as_int(v.w));
    } else {
        for (int k = e; k < nnz; k++) {
            int p = atomicAdd(&woff[rows[k]], 1);
            edges[p] = make_int2(cols[k], __float_as_int(vals[k]));
        }
    }
}

// ---------------- SpMM: warp per row, CSR, fp16 gather, fp16 out, 4-edge MLP
__global__ void spmm16_kernel(const __half* __restrict__ H,
                              const int* __restrict__ row_ptr,
                              const int2* __restrict__ edges,
                              __half* __restrict__ Hn, int N) {
    int warp = (blockIdx.x * blockDim.x + threadIdx.x) >> 5;
    int lane = threadIdx.x & 31;
    if (warp >= N) return;
    int start = row_ptr[warp];
    int end   = row_ptr[warp + 1];

    float acc[8];
    #pragma unroll
    for (int i = 0; i < 8; i++) acc[i] = 0.f;

    auto accum = [&](uint4 raw, float val) {
        const __half2* hh = (const __half2*)&raw;
        float2 f0 = __half22float2(hh[0]);
        float2 f1 = __half22float2(hh[1]);
        float2 f2 = __half22float2(hh[2]);
        float2 f3 = __half22float2(hh[3]);
        acc[0] += val * f0.x; acc[1] += val * f0.y;
        acc[2] += val * f1.x; acc[3] += val * f1.y;
        acc[4] += val * f2.x; acc[5] += val * f2.y;
        acc[6] += val * f3.x; acc[7] += val * f3.y;
    };

    for (int e0 = start; e0 < end; e0 += 32) {
        int idx = e0 + lane;
        int2 ed = make_int2(0, 0);
        if (idx < end) ed = edges[idx];
        int cnt = min(32, end - e0);
        int j = 0;
        for (; j + 4 <= cnt; j += 4) {
            int   c0 = __shfl_sync(0xffffffffu, ed.x, j + 0);
            int   c1 = __shfl_sync(0xffffffffu, ed.x, j + 1);
            int   c2 = __shfl_sync(0xffffffffu, ed.x, j + 2);
            int   c3 = __shfl_sync(0xffffffffu, ed.x, j + 3);
            float v0 = __int_as_float(__shfl_sync(0xffffffffu, ed.y, j + 0));
            float v1 = __int_as_float(__shfl_sync(0xffffffffu, ed.y, j + 1));
            float v2 = __int_as_float(__shfl_sync(0xffffffffu, ed.y, j + 2));
            float v3 = __int_as_float(__shfl_sync(0xffffffffu, ed.y, j + 3));
            uint4 r0 = ((const uint4*)(H + (size_t)c0 * DIMC))[lane];
            uint4 r1 = ((const uint4*)(H + (size_t)c1 * DIMC))[lane];
            uint4 r2 = ((const uint4*)(H + (size_t)c2 * DIMC))[lane];
            uint4 r3 = ((const uint4*)(H + (size_t)c3 * DIMC))[lane];
            accum(r0, v0);
            accum(r1, v1);
            accum(r2, v2);
            accum(r3, v3);
        }
        for (; j < cnt; j++) {
            int   col = __shfl_sync(0xffffffffu, ed.x, j);
            float val = __int_as_float(__shfl_sync(0xffffffffu, ed.y, j));
            uint4 raw = ((const uint4*)(H + (size_t)col * DIMC))[lane];
            accum(raw, val);
        }
    }
    __half2 o[4];
    o[0] = __floats2half2_rn(acc[0], acc[1]);
    o[1] = __floats2half2_rn(acc[2], acc[3]);
    o[2] = __floats2half2_rn(acc[4], acc[5]);
    o[3] = __floats2half2_rn(acc[6], acc[7]);
    ((uint4*)(Hn + (size_t)warp * DIMC))[lane] = *(uint4*)o;
}

// ---------------- tf32 tensor-core GEMM, fp16 A, 3-stage pipeline ----------
// out[M,256] = Hn16@Wn^T + Hc16@Ws^T + (bn+bs), optional ELU.
// K=512 logical (k<256 -> Hn16/Wn, else Hc16/Ws). Block 128x128, 4 warps
// (2x2), warp 64x64, BK=16. 3-stage cp.async ring, ONE __syncthreads/iter.
#define GSTR 20   // B smem row stride (floats): 16 k + 4 pad
#define ASTR 24   // A smem row stride (halves): 16 k + 8 pad

__device__ __forceinline__ unsigned f2tf32(float x) {
    unsigned r;
    asm("cvt.rna.tf32.f32 %0, %1;" : "=r"(r) : "f"(x));
    return r;
}
__device__ __forceinline__ unsigned h2tf32(__half h) {
    return __float_as_uint(__half2float(h));   // exact: fp16 mantissa fits tf32
}

__global__ __launch_bounds__(128)
void gemm_tf32_kernel(const __half* __restrict__ Hn, const __half* __restrict__ Hc,
                      const float* __restrict__ Wn, const float* __restrict__ Ws,
                      const float* __restrict__ bn, const float* __restrict__ bs,
                      float* __restrict__ out, __half* __restrict__ out16,
                      int M, int doElu) {
    __shared__ __half As[3][128 * ASTR];
    __shared__ float  Bs[3][128 * GSTR];

    int tid  = threadIdx.x;
    int lane = tid & 31;
    int wid  = tid >> 5;
    int grp  = lane >> 2;
    int tig  = lane & 3;
    int warpM = wid >> 1;
    int warpN = wid & 1;
    int rowBase = blockIdx.x * 128;
    int colBase = blockIdx.y * 128;

    int lf = tid & 3;
    int lr = tid >> 2;

    float c[4][8][4];
    #pragma unroll
    for (int mi = 0; mi < 4; mi++)
        #pragma unroll
        for (int ni = 0; ni < 8; ni++)
            #pragma unroll
            for (int r = 0; r < 4; r++) c[mi][ni][r] = 0.f;

    auto issue = [&](int it) {
        int k0 = it * 16;
        const __half* Asrc = (k0 < 256) ? Hn : Hc;
        const float*  Wsrc = (k0 < 256) ? Wn : Ws;
        int kOff = k0 & 255;
        int st = it % 3;
        #pragma unroll
        for (int i = 0; i < 2; i++) {
            int idx = tid + i * 128;
            int row = idx >> 1;
            int c8  = (idx & 1) * 8;
            int grow = rowBase + row;
            int ok = (grow < M);
            const __half* asrc = Asrc + (size_t)(ok ? grow : 0) * DIMC + kOff + c8;
            unsigned adst = (unsigned)__cvta_generic_to_shared(&As[st][row * ASTR + c8]);
            int asz = ok ? 16 : 0;
            asm volatile("cp.async.cg.shared.global [%0], [%1], 16, %2;\n"
                         :: "r"(adst), "l"(asrc), "r"(asz));
        }
        #pragma unroll
        for (int i = 0; i < 4; i++) {
            int row = lr + 32 * i;
            const float* bsrc = Wsrc + (size_t)(colBase + row) * DIMC + kOff + lf * 4;
            unsigned bdst = (unsigned)__cvta_generic_to_shared(&Bs[st][row * GSTR + lf * 4]);
            asm volatile("cp.async.cg.shared.global [%0], [%1], 16, %2;\n"
                         :: "r"(bdst), "l"(bsrc), "r"(16));
        }
        asm volatile("cp.async.commit_group;\n");
    };

    issue(0);
    issue(1);

    int st = 0;
    for (int it = 0; it < 32; it++) {
        if (it < 31) asm volatile("cp.async.wait_group 1;\n" ::: "memory");
        else         asm volatile("cp.async.wait_group 0;\n" ::: "memory");
        __syncthreads();
        if (it + 2 < 32) issue(it + 2);

        #pragma unroll
        for (int kk = 0; kk < 2; kk++) {
            unsigned a[4][4], b[8][2];
            int k = kk * 8 + tig;
            #pragma unroll
            for (int mi = 0; mi < 4; mi++) {
                int m0 = warpM * 64 + mi * 16 + grp;
                a[mi][0] = h2tf32(As[st][m0 * ASTR + k]);
                a[mi][1] = h2tf32(As[st][(m0 + 8) * ASTR + k]);
                a[mi][2] = h2tf32(As[st][m0 * ASTR + k + 4]);
                a[mi][3] = h2tf32(As[st][(m0 + 8) * ASTR + k + 4]);
            }
            #pragma unroll
            for (int ni = 0; ni < 8; ni++) {
                int n0 = warpN * 64 + ni * 8 + grp;
                b[ni][0] = f2tf32(Bs[st][n0 * GSTR + k]);
                b[ni][1] = f2tf32(Bs[st][n0 * GSTR + k + 4]);
            }
            #pragma unroll
            for (int mi = 0; mi < 4; mi++)
                #pragma unroll
                for (int ni = 0; ni < 8; ni++) {
                    asm volatile(
                        "mma.sync.aligned.m16n8k8.row.col.f32.tf32.tf32.f32 "
                        "{%0,%1,%2,%3}, {%4,%5,%6,%7}, {%8,%9}, {%0,%1,%2,%3};\n"
                        : "+f"(c[mi][ni][0]), "+f"(c[mi][ni][1]),
                          "+f"(c[mi][ni][2]), "+f"(c[mi][ni][3])
                        : "r"(a[mi][0]), "r"(a[mi][1]), "r"(a[mi][2]), "r"(a[mi][3]),
                          "r"(b[ni][0]), "r"(b[ni][1]));
                }
        }
        st = (st == 2) ? 0 : st + 1;
    }

    #pragma unroll
    for (int mi = 0; mi < 4; mi++) {
        #pragma unroll
        for (int r = 0; r < 2; r++) {
            int grow = rowBase + warpM * 64 + mi * 16 + grp + r * 8;
            if (grow >= M) continue;
            #pragma unroll
            for (int ni = 0; ni < 8; ni++) {
                int gcol = colBase + warpN * 64 + ni * 8 + tig * 2;
                float v0 = c[mi][ni][r * 2 + 0] + bn[gcol]     + bs[gcol];
                float v1 = c[mi][ni][r * 2 + 1] + bn[gcol + 1] + bs[gcol + 1];
                if (doElu) {
                    if (v0 < 0.f) v0 = expm1f(v0);
                    if (v1 < 0.f) v1 = expm1f(v1);
                }
                if (out)
                    *(float2*)(out + (size_t)grow * DIMC + gcol) = make_float2(v0, v1);
                else
                    *(__half2*)(out16 + (size_t)grow * DIMC + gcol) =
                        __floats2half2_rn(v0, v1);
            }
        }
    }
}

// ---------------- launch ----------------
extern "C" void kernel_launch(void* const* d_in, const int* in_sizes, int n_in,
                              void* d_out, int out_size) {
    const float* m    = (const float*)d_in[0];
    const float* vals = (const float*)d_in[1];
    const float* Wn   = (const float*)d_in[2];
    const float* bn   = (const float*)d_in[3];
    const float* Ws   = (const float*)d_in[4];
    const float* bs   = (const float*)d_in[5];
    const int*   rows = (const int*)d_in[6];   // int32: JAX default x64-disabled
    const int*   cols = (const int*)d_in[7];

    int N    = in_sizes[0] / DIMC;
    int nnz  = in_sizes[1];
    int hops = in_sizes[2] / (DIMC * DIMC);

    __half *Hn16, *H16a, *H16b;
    int *cnt, *rowptr, *woff;
    int2* edges;
    cudaGetSymbolAddress((void**)&Hn16,   g_Hn16);
    cudaGetSymbolAddress((void**)&H16a,   g_H16a);
    cudaGetSymbolAddress((void**)&H16b,   g_H16b);
    cudaGetSymbolAddress((void**)&edges,  g_edges);
    cudaGetSymbolAddress((void**)&cnt,    g_cnt);
    cudaGetSymbolAddress((void**)&rowptr, g_rowptr);
    cudaGetSymbolAddress((void**)&woff,   g_woff);

    // --- CSR build; f2h fused into hist (launch order: hist, scan, scatter,
    //     spmm, ... -> profiled slot #4 = SpMM) ---
    cudaMemsetAsync(cnt, 0, (size_t)N * sizeof(int), 0);
    int e4 = (nnz + 3) / 4;
    int nh2 = N * DIMC / 2;
    hist_f2h_kernel<<<(e4 + 255) / 256, 256>>>(rows, cnt, nnz, m, H16a, nh2);
    scan_kernel<<<1, 1024>>>(cnt, rowptr, woff, N, nnz);
    scatter_kernel<<<(e4 + 255) / 256, 256>>>(rows, cols, vals, woff, edges, nnz);

    // --- hop loop (single stream, proven fastest structure) ---
    float* out0 = (float*)d_out;
    int spmm_blocks = (N * 32 + 255) / 256;     // warp per row
    dim3 ggrid((N + 127) / 128, DIMC / 128);

    __half* Hcur  = H16a;
    __half* Hnext = H16b;
    for (int i = 0; i < hops; i++) {
        spmm16_kernel<<<spmm_blocks, 256>>>(Hcur, rowptr, edges, Hn16, N);
        int last = (i == hops - 1);
        gemm_tf32_kernel<<<ggrid, 128>>>(Hn16, Hcur,
                                         Wn + (size_t)i * DIMC * DIMC,
                                         Ws + (size_t)i * DIMC * DIMC,
                                         bn + (size_t)i * DIMC,
                                         bs + (size_t)i * DIMC,
                                         last ? out0 : nullptr,
                                         last ? nullptr : Hnext,
                                         N, !last);
        __half* t = Hcur; Hcur = Hnext; Hnext = t;
    }
}